// round 13
// baseline (speedup 1.0000x reference)
#include <cuda_runtime.h>
#include <cuda_bf16.h>
#include <stdint.h>
#include <cstdint>
#include <math.h>

#define N_NODES 100000
#define N_EDGES 800000
#define NF 128
#define NCLASS 40
#define N_TILES ((N_NODES + 127) / 128)   // 782

// ---------------- persistent scratch (no allocation allowed) ----------------
__device__ float g_h[N_NODES * NF];
__device__ float g_support[N_NODES * NF];
__device__ float g_support2[N_NODES * NCLASS];
__device__ int   g_deg[N_NODES];
__device__ int   g_rowptr[N_NODES + 1];
__device__ int   g_cursor[N_NODES];
__device__ int2  g_edge[N_EDGES];           // CSR-by-dst: {src, weight-as-int}
__device__ __nv_bfloat16 g_wt_hi[9 * 128 * 128];
__device__ __nv_bfloat16 g_wt_lo[9 * 128 * 128];

// ---------------- mma.sync m16n8k16 bf16 ----------------
__device__ __forceinline__ void mma16816(float& d0, float& d1, float& d2, float& d3,
                                         unsigned a0, unsigned a1, unsigned a2, unsigned a3,
                                         unsigned b0, unsigned b1) {
    asm volatile(
        "mma.sync.aligned.m16n8k16.row.col.f32.bf16.bf16.f32 "
        "{%0,%1,%2,%3}, {%4,%5,%6,%7}, {%8,%9}, {%0,%1,%2,%3};"
        : "+f"(d0), "+f"(d1), "+f"(d2), "+f"(d3)
        : "r"(a0), "r"(a1), "r"(a2), "r"(a3), "r"(b0), "r"(b1));
}

// ---------------- CSR build ----------------
__global__ void k_zero_deg() {
    int i = blockIdx.x * blockDim.x + threadIdx.x;
    if (i < N_NODES) g_deg[i] = 0;
}

__global__ void k_count(const int* __restrict__ dst) {
    int e = blockIdx.x * blockDim.x + threadIdx.x;
    if (e < N_EDGES) atomicAdd(&g_deg[dst[e]], 1);
}

__global__ void k_scan() {
    __shared__ int sp[1024];
    const int CH = (N_NODES + 1023) / 1024;   // 98
    int t = threadIdx.x;
    int b = t * CH;
    int s = 0;
    for (int i = b; i < b + CH && i < N_NODES; i++) s += g_deg[i];
    sp[t] = s;
    __syncthreads();
    for (int off = 1; off < 1024; off <<= 1) {
        int v = 0;
        if (t >= off) v = sp[t - off];
        __syncthreads();
        sp[t] += v;
        __syncthreads();
    }
    int prefix = (t == 0) ? 0 : sp[t - 1];
    for (int i = b; i < b + CH && i < N_NODES; i++) {
        g_rowptr[i] = prefix;
        g_cursor[i] = prefix;
        prefix += g_deg[i];
    }
    if (t == 1023) g_rowptr[N_NODES] = sp[1023];
}

__global__ void k_scatter(const int* __restrict__ src, const int* __restrict__ dst,
                          const float* __restrict__ ew) {
    int e = blockIdx.x * blockDim.x + threadIdx.x;
    if (e < N_EDGES) {
        int d = dst[e];
        int pos = atomicAdd(&g_cursor[d], 1);
        g_edge[pos] = make_int2(src[e], __float_as_int(ew[e]));
    }
}

// ---------------- weight transpose + hi/lo split ----------------
__global__ void k_prep_w(const float* __restrict__ W1, const float* __restrict__ W_hid) {
    int idx = blockIdx.x * blockDim.x + threadIdx.x;
    if (idx >= 9 * 16384) return;
    int m = idx >> 14;
    int r = idx & 16383;
    int n = r >> 7;
    int k = r & 127;
    float w = (m == 0) ? W1[k * 128 + n] : W_hid[(size_t)(m - 1) * 16384 + k * 128 + n];
    __nv_bfloat16 hi = __float2bfloat16(w);
    __nv_bfloat16 lo = __float2bfloat16(w - __bfloat162float(hi));
    g_wt_hi[idx] = hi;
    g_wt_lo[idx] = lo;
}

// ---------------- split-bf16 tensor-core GEMM (R11/R12 version) ----------------
#define SROW 136
#define SROWW 68
#define SM_BYTES (128 * SROW * 2)
#define SM_AHI 0
#define SM_ALO (SM_BYTES)
#define SM_BHI (2 * SM_BYTES)
#define SM_BLO (3 * SM_BYTES)
#define SMEM_GEMM_TOTAL (4 * SM_BYTES)   // 139264

__global__ void __launch_bounds__(256, 1)
k_gemm_mma(const float* __restrict__ H,
           const __nv_bfloat16* __restrict__ Bhi,
           const __nv_bfloat16* __restrict__ Blo,
           float* __restrict__ OUT) {
    extern __shared__ char smem[];
    int tid = threadIdx.x;
    int row0 = blockIdx.x * 128;

    for (int c = tid; c < 2048; c += 256) {
        int row = c >> 4;
        int k = (c & 15) << 3;
        unsigned boff = (unsigned)(row * (SROW * 2) + k * 2);

        int grow = row0 + row;
        float4 v0 = make_float4(0.f, 0.f, 0.f, 0.f), v1 = v0;
        if (grow < N_NODES) {
            v0 = __ldcs((const float4*)(H + (size_t)grow * NF + k));
            v1 = __ldcs((const float4*)(H + (size_t)grow * NF + k + 4));
        }
        float va[8] = {v0.x, v0.y, v0.z, v0.w, v1.x, v1.y, v1.z, v1.w};
        unsigned uh[4], ul[4];
#pragma unroll
        for (int i = 0; i < 4; i++) {
            __nv_bfloat16 h0 = __float2bfloat16(va[2 * i]);
            __nv_bfloat16 h1 = __float2bfloat16(va[2 * i + 1]);
            __nv_bfloat16 l0 = __float2bfloat16(va[2 * i] - __bfloat162float(h0));
            __nv_bfloat16 l1 = __float2bfloat16(va[2 * i + 1] - __bfloat162float(h1));
            uh[i] = (unsigned)__bfloat16_as_ushort(h0) | ((unsigned)__bfloat16_as_ushort(h1) << 16);
            ul[i] = (unsigned)__bfloat16_as_ushort(l0) | ((unsigned)__bfloat16_as_ushort(l1) << 16);
        }
        *(uint4*)(smem + SM_AHI + boff) = make_uint4(uh[0], uh[1], uh[2], uh[3]);
        *(uint4*)(smem + SM_ALO + boff) = make_uint4(ul[0], ul[1], ul[2], ul[3]);

        uint4 bh = *(const uint4*)(Bhi + (size_t)row * 128 + k);
        uint4 bl = *(const uint4*)(Blo + (size_t)row * 128 + k);
        *(uint4*)(smem + SM_BHI + boff) = bh;
        *(uint4*)(smem + SM_BLO + boff) = bl;
    }
    __syncthreads();

    int lane = tid & 31, w = tid >> 5;
    int wm = w & 3;
    int wn = w >> 2;
    int gid = lane >> 2;
    int tig = lane & 3;

    const unsigned* sAh = (const unsigned*)(smem + SM_AHI);
    const unsigned* sAl = (const unsigned*)(smem + SM_ALO);
    const unsigned* sBh = (const unsigned*)(smem + SM_BHI);
    const unsigned* sBl = (const unsigned*)(smem + SM_BLO);

    float acc[2][8][4];
#pragma unroll
    for (int mt = 0; mt < 2; mt++)
#pragma unroll
        for (int nt = 0; nt < 8; nt++)
#pragma unroll
            for (int i = 0; i < 4; i++) acc[mt][nt][i] = 0.f;

#pragma unroll
    for (int p = 0; p < 3; p++) {
        const unsigned* sA = (p == 2) ? sAl : sAh;
        const unsigned* sB = (p == 1) ? sBl : sBh;
#pragma unroll
        for (int ks = 0; ks < 8; ks++) {
            int kw = ks * 8;
            unsigned a[2][4];
#pragma unroll
            for (int mt = 0; mt < 2; mt++) {
                int r = wm * 32 + mt * 16;
                a[mt][0] = sA[(r + gid) * SROWW + kw + tig];
                a[mt][1] = sA[(r + gid + 8) * SROWW + kw + tig];
                a[mt][2] = sA[(r + gid) * SROWW + kw + 4 + tig];
                a[mt][3] = sA[(r + gid + 8) * SROWW + kw + 4 + tig];
            }
            unsigned b[8][2];
#pragma unroll
            for (int nt = 0; nt < 8; nt++) {
                int n = wn * 64 + nt * 8;
                b[nt][0] = sB[(n + gid) * SROWW + kw + tig];
                b[nt][1] = sB[(n + gid) * SROWW + kw + 4 + tig];
            }
#pragma unroll
            for (int mt = 0; mt < 2; mt++)
#pragma unroll
                for (int nt = 0; nt < 8; nt++)
                    mma16816(acc[mt][nt][0], acc[mt][nt][1], acc[mt][nt][2], acc[mt][nt][3],
                             a[mt][0], a[mt][1], a[mt][2], a[mt][3],
                             b[nt][0], b[nt][1]);
        }
    }

#pragma unroll
    for (int mt = 0; mt < 2; mt++) {
        int r = row0 + wm * 32 + mt * 16 + gid;
#pragma unroll
        for (int nt = 0; nt < 8; nt++) {
            int cN = wn * 64 + nt * 8 + tig * 2;
            if (r < N_NODES)
                *(float2*)(OUT + (size_t)r * 128 + cN) = make_float2(acc[mt][nt][0], acc[mt][nt][1]);
            if (r + 8 < N_NODES)
                *(float2*)(OUT + (size_t)(r + 8) * 128 + cN) = make_float2(acc[mt][nt][2], acc[mt][nt][3]);
        }
    }
}

// ---------------- final GEMM: g_support2[N,40] = H[N,128] @ W10[128,40] ----------------
__global__ __launch_bounds__(256) void k_gemm40(const float* __restrict__ H,
                                                const float* __restrict__ W) {
    __shared__ float sW[128 * NCLASS];
    int tid = threadIdx.x;
    for (int i = tid; i < 128 * NCLASS; i += 256) sW[i] = W[i];
    __syncthreads();
    int row = blockIdx.x * 256 + tid;
    if (row >= N_NODES) return;
    float acc[NCLASS];
#pragma unroll
    for (int j = 0; j < NCLASS; j++) acc[j] = 0.f;
    for (int k = 0; k < 128; k += 4) {
        float4 h4 = __ldcs((const float4*)(H + (size_t)row * NF + k));
#pragma unroll
        for (int j4 = 0; j4 < 10; j4++) {
            float4 w0 = *(const float4*)&sW[(k + 0) * NCLASS + j4 * 4];
            float4 w1 = *(const float4*)&sW[(k + 1) * NCLASS + j4 * 4];
            float4 w2 = *(const float4*)&sW[(k + 2) * NCLASS + j4 * 4];
            float4 w3 = *(const float4*)&sW[(k + 3) * NCLASS + j4 * 4];
            acc[j4 * 4 + 0] += h4.x * w0.x + h4.y * w1.x + h4.z * w2.x + h4.w * w3.x;
            acc[j4 * 4 + 1] += h4.x * w0.y + h4.y * w1.y + h4.z * w2.y + h4.w * w3.y;
            acc[j4 * 4 + 2] += h4.x * w0.z + h4.y * w1.z + h4.z * w2.z + h4.w * w3.z;
            acc[j4 * 4 + 3] += h4.x * w0.w + h4.y * w1.w + h4.z * w2.w + h4.w * w3.w;
        }
    }
#pragma unroll
    for (int j = 0; j < NCLASS; j++) g_support2[(size_t)row * NCLASS + j] = acc[j];
}

// ---------------- SpMM + bias + relu (+residual), warp per node ----------------
// unroll-16 chunks with software-pipelined edge loads.
__global__ __launch_bounds__(256) void k_spmm(const float* __restrict__ sup,
                                              const float* __restrict__ bias,
                                              int residual) {
    int gwarp = (blockIdx.x * blockDim.x + threadIdx.x) >> 5;
    int lane  = threadIdx.x & 31;
    if (gwarp >= N_NODES) return;
    int beg = g_rowptr[gwarp];
    int end = g_rowptr[gwarp + 1];
    int count = end - beg;
    float4 acc = make_float4(0.f, 0.f, 0.f, 0.f);

    // prefetch first edge chunk
    int s = 0; float w = 0.f;
    if (lane < 16 && lane < count) {
        int2 e = __ldcs(&g_edge[beg + lane]);
        s = e.x; w = __int_as_float(e.y);
    }

    for (int base = 0; base < count; base += 16) {
        int m = count - base;
        int cs = s; float cw = w;
        // prefetch next chunk's edges before the gather loop
        int nb = base + 16;
        if (nb < count && lane < 16 && nb + lane < count) {
            int2 e = __ldcs(&g_edge[beg + nb + lane]);
            s = e.x; w = __int_as_float(e.y);
        }
#pragma unroll
        for (int j = 0; j < 16; j++) {
            int   ss = __shfl_sync(0xffffffffu, cs, j);
            float ww = __shfl_sync(0xffffffffu, cw, j);
            if (j < m) {
                float4 v = *(const float4*)(sup + (size_t)ss * NF + lane * 4);
                acc.x += ww * v.x; acc.y += ww * v.y; acc.z += ww * v.z; acc.w += ww * v.w;
            }
        }
    }
    float4 b = *(const float4*)(bias + lane * 4);
    float4 r;
    r.x = fmaxf(acc.x + b.x, 0.f);
    r.y = fmaxf(acc.y + b.y, 0.f);
    r.z = fmaxf(acc.z + b.z, 0.f);
    r.w = fmaxf(acc.w + b.w, 0.f);
    float* hrow = g_h + (size_t)gwarp * NF + lane * 4;
    if (residual) {
        float4 hv = __ldcs((const float4*)hrow);
        r.x += hv.x; r.y += hv.y; r.z += hv.z; r.w += hv.w;
    }
    __stcs((float4*)hrow, r);
}

// ---------------- final SpMM(40) + bias + relu + log_softmax ----------------
__global__ __launch_bounds__(256) void k_spmm40_softmax(const float* __restrict__ b10,
                                                        float* __restrict__ out) {
    int gwarp = (blockIdx.x * blockDim.x + threadIdx.x) >> 5;
    int lane  = threadIdx.x & 31;
    if (gwarp >= N_NODES) return;
    int beg = g_rowptr[gwarp];
    int end = g_rowptr[gwarp + 1];
    int count = end - beg;
    float a0 = 0.f, a1 = 0.f;

    int s = 0; float w = 0.f;
    if (lane < 16 && lane < count) {
        int2 e = __ldcs(&g_edge[beg + lane]);
        s = e.x; w = __int_as_float(e.y);
    }
    for (int base = 0; base < count; base += 16) {
        int m = count - base;
        int cs = s; float cw = w;
        int nb = base + 16;
        if (nb < count && lane < 16 && nb + lane < count) {
            int2 e = __ldcs(&g_edge[beg + nb + lane]);
            s = e.x; w = __int_as_float(e.y);
        }
#pragma unroll
        for (int j = 0; j < 16; j++) {
            int   ss = __shfl_sync(0xffffffffu, cs, j);
            float ww = __shfl_sync(0xffffffffu, cw, j);
            if (j < m) {
                a0 += ww * g_support2[(size_t)ss * NCLASS + lane];
                if (lane < 8) a1 += ww * g_support2[(size_t)ss * NCLASS + 32 + lane];
            }
        }
    }
    float v0 = fmaxf(a0 + b10[lane], 0.f);
    float v1 = (lane < 8) ? fmaxf(a1 + b10[32 + lane], 0.f) : -1e30f;
    float mx = fmaxf(v0, v1);
#pragma unroll
    for (int off = 16; off > 0; off >>= 1)
        mx = fmaxf(mx, __shfl_xor_sync(0xffffffffu, mx, off));
    float se = expf(v0 - mx) + ((lane < 8) ? expf(v1 - mx) : 0.f);
#pragma unroll
    for (int off = 16; off > 0; off >>= 1)
        se += __shfl_xor_sync(0xffffffffu, se, off);
    float ls = logf(se);
    out[(size_t)gwarp * NCLASS + lane] = v0 - mx - ls;
    if (lane < 8) out[(size_t)gwarp * NCLASS + 32 + lane] = v1 - mx - ls;
}

// ---------------- launcher ----------------
extern "C" void kernel_launch(void* const* d_in, const int* in_sizes, int n_in,
                              void* d_out, int out_size) {
    const float* x     = (const float*)d_in[0];
    const int*   src   = (const int*)d_in[1];
    const int*   dst   = (const int*)d_in[2];
    const float* ew    = (const float*)d_in[3];
    const float* W1    = (const float*)d_in[4];
    const float* W_hid = (const float*)d_in[5];
    const float* W10   = (const float*)d_in[6];
    const float* b1    = (const float*)d_in[7];
    const float* b_hid = (const float*)d_in[8];
    const float* b10   = (const float*)d_in[9];
    float* out = (float*)d_out;

    float *p_h, *p_sup;
    __nv_bfloat16 *p_whi, *p_wlo;
    cudaGetSymbolAddress((void**)&p_h, g_h);
    cudaGetSymbolAddress((void**)&p_sup, g_support);
    cudaGetSymbolAddress((void**)&p_whi, g_wt_hi);
    cudaGetSymbolAddress((void**)&p_wlo, g_wt_lo);

    cudaFuncSetAttribute(k_gemm_mma, cudaFuncAttributeMaxDynamicSharedMemorySize,
                         SMEM_GEMM_TOTAL);

    // CSR build + weight prep (per call; deterministic)
    k_zero_deg<<<(N_NODES + 255) / 256, 256>>>();
    k_count<<<(N_EDGES + 255) / 256, 256>>>(dst);
    k_scan<<<1, 1024>>>();
    k_scatter<<<(N_EDGES + 255) / 256, 256>>>(src, dst, ew);
    k_prep_w<<<(9 * 16384 + 255) / 256, 256>>>(W1, W_hid);

    dim3 gs((N_NODES * 32 + 255) / 256);

    // layer 1: h = relu(spmm(x @ W1) + b1)
    k_gemm_mma<<<N_TILES, 256, SMEM_GEMM_TOTAL>>>(x, p_whi, p_wlo, p_sup);
    k_spmm<<<gs, 256>>>(p_sup, b1, 0);

    // 8 hidden residual layers
    for (int i = 0; i < 8; i++) {
        k_gemm_mma<<<N_TILES, 256, SMEM_GEMM_TOTAL>>>(
            p_h, p_whi + (size_t)(i + 1) * 16384, p_wlo + (size_t)(i + 1) * 16384, p_sup);
        k_spmm<<<gs, 256>>>(p_sup, b_hid + (size_t)i * 128, 1);
    }

    // final layer + log_softmax
    k_gemm40<<<(N_NODES + 255) / 256, 256>>>(p_h, W10);
    k_spmm40_softmax<<<gs, 256>>>(b10, out);
}

// round 14
// speedup vs baseline: 1.0372x; 1.0372x over previous
#include <cuda_runtime.h>
#include <cuda_bf16.h>
#include <stdint.h>
#include <cstdint>
#include <math.h>

#define N_NODES 100000
#define N_EDGES 800000
#define NF 128
#define NCLASS 40
#define N_TILES ((N_NODES + 127) / 128)   // 782

// ---------------- persistent scratch (no allocation allowed) ----------------
__device__ float g_h[N_NODES * NF];
__device__ float g_support[N_NODES * NF];
__device__ float g_support2[N_NODES * NCLASS];
__device__ int   g_deg[N_NODES];
__device__ int   g_rowptr[N_NODES + 1];
__device__ int   g_cursor[N_NODES];
__device__ int2  g_edge[N_EDGES];           // CSR-by-dst: {src, weight-as-int}
__device__ __nv_bfloat16 g_wt_hi[9 * 128 * 128];
__device__ __nv_bfloat16 g_wt_lo[9 * 128 * 128];

// ---------------- mma.sync m16n8k16 bf16 ----------------
__device__ __forceinline__ void mma16816(float& d0, float& d1, float& d2, float& d3,
                                         unsigned a0, unsigned a1, unsigned a2, unsigned a3,
                                         unsigned b0, unsigned b1) {
    asm volatile(
        "mma.sync.aligned.m16n8k16.row.col.f32.bf16.bf16.f32 "
        "{%0,%1,%2,%3}, {%4,%5,%6,%7}, {%8,%9}, {%0,%1,%2,%3};"
        : "+f"(d0), "+f"(d1), "+f"(d2), "+f"(d3)
        : "r"(a0), "r"(a1), "r"(a2), "r"(a3), "r"(b0), "r"(b1));
}

// ---------------- CSR build ----------------
__global__ void k_count(const int* __restrict__ dst) {
    int e = blockIdx.x * blockDim.x + threadIdx.x;
    if (e < N_EDGES) atomicAdd(&g_deg[dst[e]], 1);
}

__global__ void k_scan() {
    __shared__ int sp[1024];
    const int CH = (N_NODES + 1023) / 1024;   // 98
    int t = threadIdx.x;
    int b = t * CH;
    int s = 0;
    for (int i = b; i < b + CH && i < N_NODES; i++) s += g_deg[i];
    sp[t] = s;
    __syncthreads();
    for (int off = 1; off < 1024; off <<= 1) {
        int v = 0;
        if (t >= off) v = sp[t - off];
        __syncthreads();
        sp[t] += v;
        __syncthreads();
    }
    int prefix = (t == 0) ? 0 : sp[t - 1];
    for (int i = b; i < b + CH && i < N_NODES; i++) {
        g_rowptr[i] = prefix;
        g_cursor[i] = prefix;
        prefix += g_deg[i];
    }
    if (t == 1023) g_rowptr[N_NODES] = sp[1023];
}

__global__ void k_scatter(const int* __restrict__ src, const int* __restrict__ dst,
                          const float* __restrict__ ew) {
    int e = blockIdx.x * blockDim.x + threadIdx.x;
    if (e < N_EDGES) {
        int d = dst[e];
        int pos = atomicAdd(&g_cursor[d], 1);
        g_edge[pos] = make_int2(src[e], __float_as_int(ew[e]));
    }
}

// ---------------- weight transpose + hi/lo split ----------------
__global__ void k_prep_w(const float* __restrict__ W1, const float* __restrict__ W_hid) {
    int idx = blockIdx.x * blockDim.x + threadIdx.x;
    if (idx >= 9 * 16384) return;
    int m = idx >> 14;
    int r = idx & 16383;
    int n = r >> 7;
    int k = r & 127;
    float w = (m == 0) ? W1[k * 128 + n] : W_hid[(size_t)(m - 1) * 16384 + k * 128 + n];
    __nv_bfloat16 hi = __float2bfloat16(w);
    __nv_bfloat16 lo = __float2bfloat16(w - __bfloat162float(hi));
    g_wt_hi[idx] = hi;
    g_wt_lo[idx] = lo;
}

// ---------------- split-bf16 tensor-core GEMM (R12 version) ----------------
#define SROW 136
#define SROWW 68
#define SM_BYTES (128 * SROW * 2)
#define SM_AHI 0
#define SM_ALO (SM_BYTES)
#define SM_BHI (2 * SM_BYTES)
#define SM_BLO (3 * SM_BYTES)
#define SMEM_GEMM_TOTAL (4 * SM_BYTES)   // 139264

__global__ void __launch_bounds__(256, 1)
k_gemm_mma(const float* __restrict__ H,
           const __nv_bfloat16* __restrict__ Bhi,
           const __nv_bfloat16* __restrict__ Blo,
           float* __restrict__ OUT) {
    extern __shared__ char smem[];
    int tid = threadIdx.x;
    int row0 = blockIdx.x * 128;

    for (int c = tid; c < 2048; c += 256) {
        int row = c >> 4;
        int k = (c & 15) << 3;
        unsigned boff = (unsigned)(row * (SROW * 2) + k * 2);

        int grow = row0 + row;
        float4 v0 = make_float4(0.f, 0.f, 0.f, 0.f), v1 = v0;
        if (grow < N_NODES) {
            v0 = __ldcs((const float4*)(H + (size_t)grow * NF + k));
            v1 = __ldcs((const float4*)(H + (size_t)grow * NF + k + 4));
        }
        float va[8] = {v0.x, v0.y, v0.z, v0.w, v1.x, v1.y, v1.z, v1.w};
        unsigned uh[4], ul[4];
#pragma unroll
        for (int i = 0; i < 4; i++) {
            __nv_bfloat16 h0 = __float2bfloat16(va[2 * i]);
            __nv_bfloat16 h1 = __float2bfloat16(va[2 * i + 1]);
            __nv_bfloat16 l0 = __float2bfloat16(va[2 * i] - __bfloat162float(h0));
            __nv_bfloat16 l1 = __float2bfloat16(va[2 * i + 1] - __bfloat162float(h1));
            uh[i] = (unsigned)__bfloat16_as_ushort(h0) | ((unsigned)__bfloat16_as_ushort(h1) << 16);
            ul[i] = (unsigned)__bfloat16_as_ushort(l0) | ((unsigned)__bfloat16_as_ushort(l1) << 16);
        }
        *(uint4*)(smem + SM_AHI + boff) = make_uint4(uh[0], uh[1], uh[2], uh[3]);
        *(uint4*)(smem + SM_ALO + boff) = make_uint4(ul[0], ul[1], ul[2], ul[3]);

        uint4 bh = *(const uint4*)(Bhi + (size_t)row * 128 + k);
        uint4 bl = *(const uint4*)(Blo + (size_t)row * 128 + k);
        *(uint4*)(smem + SM_BHI + boff) = bh;
        *(uint4*)(smem + SM_BLO + boff) = bl;
    }
    __syncthreads();

    int lane = tid & 31, w = tid >> 5;
    int wm = w & 3;
    int wn = w >> 2;
    int gid = lane >> 2;
    int tig = lane & 3;

    const unsigned* sAh = (const unsigned*)(smem + SM_AHI);
    const unsigned* sAl = (const unsigned*)(smem + SM_ALO);
    const unsigned* sBh = (const unsigned*)(smem + SM_BHI);
    const unsigned* sBl = (const unsigned*)(smem + SM_BLO);

    float acc[2][8][4];
#pragma unroll
    for (int mt = 0; mt < 2; mt++)
#pragma unroll
        for (int nt = 0; nt < 8; nt++)
#pragma unroll
            for (int i = 0; i < 4; i++) acc[mt][nt][i] = 0.f;

#pragma unroll
    for (int p = 0; p < 3; p++) {
        const unsigned* sA = (p == 2) ? sAl : sAh;
        const unsigned* sB = (p == 1) ? sBl : sBh;
#pragma unroll
        for (int ks = 0; ks < 8; ks++) {
            int kw = ks * 8;
            unsigned a[2][4];
#pragma unroll
            for (int mt = 0; mt < 2; mt++) {
                int r = wm * 32 + mt * 16;
                a[mt][0] = sA[(r + gid) * SROWW + kw + tig];
                a[mt][1] = sA[(r + gid + 8) * SROWW + kw + tig];
                a[mt][2] = sA[(r + gid) * SROWW + kw + 4 + tig];
                a[mt][3] = sA[(r + gid + 8) * SROWW + kw + 4 + tig];
            }
            unsigned b[8][2];
#pragma unroll
            for (int nt = 0; nt < 8; nt++) {
                int n = wn * 64 + nt * 8;
                b[nt][0] = sB[(n + gid) * SROWW + kw + tig];
                b[nt][1] = sB[(n + gid) * SROWW + kw + 4 + tig];
            }
#pragma unroll
            for (int mt = 0; mt < 2; mt++)
#pragma unroll
                for (int nt = 0; nt < 8; nt++)
                    mma16816(acc[mt][nt][0], acc[mt][nt][1], acc[mt][nt][2], acc[mt][nt][3],
                             a[mt][0], a[mt][1], a[mt][2], a[mt][3],
                             b[nt][0], b[nt][1]);
        }
    }

#pragma unroll
    for (int mt = 0; mt < 2; mt++) {
        int r = row0 + wm * 32 + mt * 16 + gid;
#pragma unroll
        for (int nt = 0; nt < 8; nt++) {
            int cN = wn * 64 + nt * 8 + tig * 2;
            if (r < N_NODES)
                *(float2*)(OUT + (size_t)r * 128 + cN) = make_float2(acc[mt][nt][0], acc[mt][nt][1]);
            if (r + 8 < N_NODES)
                *(float2*)(OUT + (size_t)(r + 8) * 128 + cN) = make_float2(acc[mt][nt][2], acc[mt][nt][3]);
        }
    }
}

// ---------------- final GEMM: g_support2[N,40] = H[N,128] @ W10[128,40] ----------------
__global__ __launch_bounds__(256) void k_gemm40(const float* __restrict__ H,
                                                const float* __restrict__ W) {
    __shared__ float sW[128 * NCLASS];
    int tid = threadIdx.x;
    for (int i = tid; i < 128 * NCLASS; i += 256) sW[i] = W[i];
    __syncthreads();
    int row = blockIdx.x * 256 + tid;
    if (row >= N_NODES) return;
    float acc[NCLASS];
#pragma unroll
    for (int j = 0; j < NCLASS; j++) acc[j] = 0.f;
    for (int k = 0; k < 128; k += 4) {
        float4 h4 = __ldcs((const float4*)(H + (size_t)row * NF + k));
#pragma unroll
        for (int j4 = 0; j4 < 10; j4++) {
            float4 w0 = *(const float4*)&sW[(k + 0) * NCLASS + j4 * 4];
            float4 w1 = *(const float4*)&sW[(k + 1) * NCLASS + j4 * 4];
            float4 w2 = *(const float4*)&sW[(k + 2) * NCLASS + j4 * 4];
            float4 w3 = *(const float4*)&sW[(k + 3) * NCLASS + j4 * 4];
            acc[j4 * 4 + 0] += h4.x * w0.x + h4.y * w1.x + h4.z * w2.x + h4.w * w3.x;
            acc[j4 * 4 + 1] += h4.x * w0.y + h4.y * w1.y + h4.z * w2.y + h4.w * w3.y;
            acc[j4 * 4 + 2] += h4.x * w0.z + h4.y * w1.z + h4.z * w2.z + h4.w * w3.z;
            acc[j4 * 4 + 3] += h4.x * w0.w + h4.y * w1.w + h4.z * w2.w + h4.w * w3.w;
        }
    }
#pragma unroll
    for (int j = 0; j < NCLASS; j++) g_support2[(size_t)row * NCLASS + j] = acc[j];
}

// ---------------- SpMM + bias + relu (+residual), warp per node ----------------
// R12 version: predicated unroll-8 chunks.
__global__ __launch_bounds__(256) void k_spmm(const float* __restrict__ sup,
                                              const float* __restrict__ bias,
                                              int residual) {
    int gwarp = (blockIdx.x * blockDim.x + threadIdx.x) >> 5;
    int lane  = threadIdx.x & 31;
    if (gwarp >= N_NODES) return;
    int beg = g_rowptr[gwarp];
    int end = g_rowptr[gwarp + 1];
    float4 acc = make_float4(0.f, 0.f, 0.f, 0.f);
    int count = end - beg;
    for (int base = 0; base < count; base += 8) {
        int m = count - base;
        int s = 0; float w = 0.f;
        if (lane < 8 && lane < m) {
            int2 e = __ldcs(&g_edge[beg + base + lane]);
            s = e.x; w = __int_as_float(e.y);
        }
#pragma unroll
        for (int j = 0; j < 8; j++) {
            int   ss = __shfl_sync(0xffffffffu, s, j);
            float ww = __shfl_sync(0xffffffffu, w, j);
            if (j < m) {
                float4 v = *(const float4*)(sup + (size_t)ss * NF + lane * 4);
                acc.x += ww * v.x; acc.y += ww * v.y; acc.z += ww * v.z; acc.w += ww * v.w;
            }
        }
    }
    float4 b = *(const float4*)(bias + lane * 4);
    float4 r;
    r.x = fmaxf(acc.x + b.x, 0.f);
    r.y = fmaxf(acc.y + b.y, 0.f);
    r.z = fmaxf(acc.z + b.z, 0.f);
    r.w = fmaxf(acc.w + b.w, 0.f);
    float* hrow = g_h + (size_t)gwarp * NF + lane * 4;
    if (residual) {
        float4 hv = __ldcs((const float4*)hrow);
        r.x += hv.x; r.y += hv.y; r.z += hv.z; r.w += hv.w;
    }
    __stcs((float4*)hrow, r);
}

// ---------------- final SpMM(40) + bias + relu + log_softmax ----------------
__global__ __launch_bounds__(256) void k_spmm40_softmax(const float* __restrict__ b10,
                                                        float* __restrict__ out) {
    int gwarp = (blockIdx.x * blockDim.x + threadIdx.x) >> 5;
    int lane  = threadIdx.x & 31;
    if (gwarp >= N_NODES) return;
    int beg = g_rowptr[gwarp];
    int end = g_rowptr[gwarp + 1];
    float a0 = 0.f, a1 = 0.f;
    int count = end - beg;
    for (int base = 0; base < count; base += 8) {
        int m = count - base;
        int s = 0; float w = 0.f;
        if (lane < 8 && lane < m) {
            int2 e = __ldcs(&g_edge[beg + base + lane]);
            s = e.x; w = __int_as_float(e.y);
        }
#pragma unroll
        for (int j = 0; j < 8; j++) {
            int   ss = __shfl_sync(0xffffffffu, s, j);
            float ww = __shfl_sync(0xffffffffu, w, j);
            if (j < m) {
                a0 += ww * g_support2[(size_t)ss * NCLASS + lane];
                if (lane < 8) a1 += ww * g_support2[(size_t)ss * NCLASS + 32 + lane];
            }
        }
    }
    float v0 = fmaxf(a0 + b10[lane], 0.f);
    float v1 = (lane < 8) ? fmaxf(a1 + b10[32 + lane], 0.f) : -1e30f;
    float mx = fmaxf(v0, v1);
#pragma unroll
    for (int off = 16; off > 0; off >>= 1)
        mx = fmaxf(mx, __shfl_xor_sync(0xffffffffu, mx, off));
    float se = expf(v0 - mx) + ((lane < 8) ? expf(v1 - mx) : 0.f);
#pragma unroll
    for (int off = 16; off > 0; off >>= 1)
        se += __shfl_xor_sync(0xffffffffu, se, off);
    float ls = logf(se);
    out[(size_t)gwarp * NCLASS + lane] = v0 - mx - ls;
    if (lane < 8) out[(size_t)gwarp * NCLASS + 32 + lane] = v1 - mx - ls;
}

// ---------------- launcher ----------------
extern "C" void kernel_launch(void* const* d_in, const int* in_sizes, int n_in,
                              void* d_out, int out_size) {
    const float* x     = (const float*)d_in[0];
    const int*   src   = (const int*)d_in[1];
    const int*   dst   = (const int*)d_in[2];
    const float* ew    = (const float*)d_in[3];
    const float* W1    = (const float*)d_in[4];
    const float* W_hid = (const float*)d_in[5];
    const float* W10   = (const float*)d_in[6];
    const float* b1    = (const float*)d_in[7];
    const float* b_hid = (const float*)d_in[8];
    const float* b10   = (const float*)d_in[9];
    float* out = (float*)d_out;

    float *p_h, *p_sup;
    int* p_deg;
    __nv_bfloat16 *p_whi, *p_wlo;
    cudaGetSymbolAddress((void**)&p_h, g_h);
    cudaGetSymbolAddress((void**)&p_sup, g_support);
    cudaGetSymbolAddress((void**)&p_deg, g_deg);
    cudaGetSymbolAddress((void**)&p_whi, g_wt_hi);
    cudaGetSymbolAddress((void**)&p_wlo, g_wt_lo);

    cudaFuncSetAttribute(k_gemm_mma, cudaFuncAttributeMaxDynamicSharedMemorySize,
                         SMEM_GEMM_TOTAL);

    dim3 gs((N_NODES * 32 + 255) / 256);

    // Launch order arranged so the 4th kernel is k_gemm_mma (ncu -s 5 -c 1 capture).
    // Dependencies preserved by stream order: count<-memset, scan<-count,
    // gemm<-prep_w, scatter<-scan, spmm<-{gemm, scatter}.
    cudaMemsetAsync(p_deg, 0, N_NODES * sizeof(int));
    k_count<<<(N_EDGES + 255) / 256, 256>>>(dst);      // 1
    k_scan<<<1, 1024>>>();                             // 2
    k_prep_w<<<(9 * 16384 + 255) / 256, 256>>>(W1, W_hid);  // 3
    k_gemm_mma<<<N_TILES, 256, SMEM_GEMM_TOTAL>>>(x, p_whi, p_wlo, p_sup);  // 4 <- profiled
    k_scatter<<<(N_EDGES + 255) / 256, 256>>>(src, dst, ew);                // 5
    k_spmm<<<gs, 256>>>(p_sup, b1, 0);                                      // 6

    // 8 hidden residual layers
    for (int i = 0; i < 8; i++) {
        k_gemm_mma<<<N_TILES, 256, SMEM_GEMM_TOTAL>>>(
            p_h, p_whi + (size_t)(i + 1) * 16384, p_wlo + (size_t)(i + 1) * 16384, p_sup);
        k_spmm<<<gs, 256>>>(p_sup, b_hid + (size_t)i * 128, 1);
    }

    // final layer + log_softmax
    k_gemm40<<<(N_NODES + 255) / 256, 256>>>(p_h, W10);
    k_spmm40_softmax<<<gs, 256>>>(b10, out);
}

// round 15
// speedup vs baseline: 1.0882x; 1.0492x over previous
#include <cuda_runtime.h>
#include <cuda_bf16.h>
#include <stdint.h>
#include <cstdint>
#include <math.h>

#define N_NODES 100000
#define N_EDGES 800000
#define NF 128
#define NCLASS 40
#define N_TILES ((N_NODES + 127) / 128)   // 782

// ---------------- persistent scratch (no allocation allowed) ----------------
__device__ float g_h[N_NODES * NF];
__device__ float g_support[N_NODES * NF];
__device__ float g_support2[N_NODES * NCLASS];
__device__ int   g_deg[N_NODES];
__device__ int   g_rowptr[N_NODES + 1];
__device__ int   g_cursor[N_NODES];
__device__ int2  g_edge[N_EDGES];           // CSR-by-dst: {src, weight-as-int}
__device__ __nv_bfloat16 g_wt_hi[9 * 128 * 128];
__device__ __nv_bfloat16 g_wt_lo[9 * 128 * 128];

// ---------------- mma.sync m16n8k16 bf16 ----------------
__device__ __forceinline__ void mma16816(float& d0, float& d1, float& d2, float& d3,
                                         unsigned a0, unsigned a1, unsigned a2, unsigned a3,
                                         unsigned b0, unsigned b1) {
    asm volatile(
        "mma.sync.aligned.m16n8k16.row.col.f32.bf16.bf16.f32 "
        "{%0,%1,%2,%3}, {%4,%5,%6,%7}, {%8,%9}, {%0,%1,%2,%3};"
        : "+f"(d0), "+f"(d1), "+f"(d2), "+f"(d3)
        : "r"(a0), "r"(a1), "r"(a2), "r"(a3), "r"(b0), "r"(b1));
}

// ---------------- CSR build ----------------
__global__ void k_count(const int* __restrict__ dst) {
    int e = blockIdx.x * blockDim.x + threadIdx.x;
    if (e < N_EDGES) atomicAdd(&g_deg[dst[e]], 1);
}

__global__ void k_scan() {
    __shared__ int sp[1024];
    const int CH = (N_NODES + 1023) / 1024;   // 98
    int t = threadIdx.x;
    int b = t * CH;
    int s = 0;
    for (int i = b; i < b + CH && i < N_NODES; i++) s += g_deg[i];
    sp[t] = s;
    __syncthreads();
    for (int off = 1; off < 1024; off <<= 1) {
        int v = 0;
        if (t >= off) v = sp[t - off];
        __syncthreads();
        sp[t] += v;
        __syncthreads();
    }
    int prefix = (t == 0) ? 0 : sp[t - 1];
    for (int i = b; i < b + CH && i < N_NODES; i++) {
        g_rowptr[i] = prefix;
        g_cursor[i] = prefix;
        prefix += g_deg[i];
    }
    if (t == 1023) g_rowptr[N_NODES] = sp[1023];
}

__global__ void k_scatter(const int* __restrict__ src, const int* __restrict__ dst,
                          const float* __restrict__ ew) {
    int e = blockIdx.x * blockDim.x + threadIdx.x;
    if (e < N_EDGES) {
        int d = dst[e];
        int pos = atomicAdd(&g_cursor[d], 1);
        g_edge[pos] = make_int2(src[e], __float_as_int(ew[e]));
    }
}

// ---------------- weight transpose + hi/lo split ----------------
__global__ void k_prep_w(const float* __restrict__ W1, const float* __restrict__ W_hid) {
    int idx = blockIdx.x * blockDim.x + threadIdx.x;
    if (idx >= 9 * 16384) return;
    int m = idx >> 14;
    int r = idx & 16383;
    int n = r >> 7;
    int k = r & 127;
    float w = (m == 0) ? W1[k * 128 + n] : W_hid[(size_t)(m - 1) * 16384 + k * 128 + n];
    __nv_bfloat16 hi = __float2bfloat16(w);
    __nv_bfloat16 lo = __float2bfloat16(w - __bfloat162float(hi));
    g_wt_hi[idx] = hi;
    g_wt_lo[idx] = lo;
}

// ---------------- split-bf16 tensor-core GEMM: 512 threads, 16 warps ----------------
#define SROW 136
#define SROWW 68
#define SM_BYTES (128 * SROW * 2)
#define SM_AHI 0
#define SM_ALO (SM_BYTES)
#define SM_BHI (2 * SM_BYTES)
#define SM_BLO (3 * SM_BYTES)
#define SMEM_GEMM_TOTAL (4 * SM_BYTES)   // 139264

__global__ void __launch_bounds__(512, 1)
k_gemm_mma(const float* __restrict__ H,
           const __nv_bfloat16* __restrict__ Bhi,
           const __nv_bfloat16* __restrict__ Blo,
           float* __restrict__ OUT) {
    extern __shared__ char smem[];
    int tid = threadIdx.x;
    int row0 = blockIdx.x * 128;

    // ---- fill: A fp32 -> hi/lo bf16, B bf16 copy; 2048 chunks over 512 threads ----
    for (int c = tid; c < 2048; c += 512) {
        int row = c >> 4;
        int k = (c & 15) << 3;
        unsigned boff = (unsigned)(row * (SROW * 2) + k * 2);

        int grow = row0 + row;
        float4 v0 = make_float4(0.f, 0.f, 0.f, 0.f), v1 = v0;
        if (grow < N_NODES) {
            v0 = __ldcs((const float4*)(H + (size_t)grow * NF + k));
            v1 = __ldcs((const float4*)(H + (size_t)grow * NF + k + 4));
        }
        float va[8] = {v0.x, v0.y, v0.z, v0.w, v1.x, v1.y, v1.z, v1.w};
        unsigned uh[4], ul[4];
#pragma unroll
        for (int i = 0; i < 4; i++) {
            __nv_bfloat16 h0 = __float2bfloat16(va[2 * i]);
            __nv_bfloat16 h1 = __float2bfloat16(va[2 * i + 1]);
            __nv_bfloat16 l0 = __float2bfloat16(va[2 * i] - __bfloat162float(h0));
            __nv_bfloat16 l1 = __float2bfloat16(va[2 * i + 1] - __bfloat162float(h1));
            uh[i] = (unsigned)__bfloat16_as_ushort(h0) | ((unsigned)__bfloat16_as_ushort(h1) << 16);
            ul[i] = (unsigned)__bfloat16_as_ushort(l0) | ((unsigned)__bfloat16_as_ushort(l1) << 16);
        }
        *(uint4*)(smem + SM_AHI + boff) = make_uint4(uh[0], uh[1], uh[2], uh[3]);
        *(uint4*)(smem + SM_ALO + boff) = make_uint4(ul[0], ul[1], ul[2], ul[3]);

        uint4 bh = *(const uint4*)(Bhi + (size_t)row * 128 + k);
        uint4 bl = *(const uint4*)(Blo + (size_t)row * 128 + k);
        *(uint4*)(smem + SM_BHI + boff) = bh;
        *(uint4*)(smem + SM_BLO + boff) = bl;
    }
    __syncthreads();

    // ---- warp tiling: 16 warps = 4 (m) x 4 (n); warp tile 32 x 32 ----
    int lane = tid & 31, w = tid >> 5;
    int wm = w & 3;          // rows wm*32
    int wn = w >> 2;         // cols wn*32
    int gid = lane >> 2;     // 0..7
    int tig = lane & 3;      // 0..3

    const unsigned* sAh = (const unsigned*)(smem + SM_AHI);
    const unsigned* sAl = (const unsigned*)(smem + SM_ALO);
    const unsigned* sBh = (const unsigned*)(smem + SM_BHI);
    const unsigned* sBl = (const unsigned*)(smem + SM_BLO);

    float acc[2][4][4];
#pragma unroll
    for (int mt = 0; mt < 2; mt++)
#pragma unroll
        for (int nt = 0; nt < 4; nt++)
#pragma unroll
            for (int i = 0; i < 4; i++) acc[mt][nt][i] = 0.f;

#pragma unroll
    for (int p = 0; p < 3; p++) {
        const unsigned* sA = (p == 2) ? sAl : sAh;
        const unsigned* sB = (p == 1) ? sBl : sBh;
#pragma unroll
        for (int ks = 0; ks < 8; ks++) {
            int kw = ks * 8;
            unsigned a[2][4];
#pragma unroll
            for (int mt = 0; mt < 2; mt++) {
                int r = wm * 32 + mt * 16;
                a[mt][0] = sA[(r + gid) * SROWW + kw + tig];
                a[mt][1] = sA[(r + gid + 8) * SROWW + kw + tig];
                a[mt][2] = sA[(r + gid) * SROWW + kw + 4 + tig];
                a[mt][3] = sA[(r + gid + 8) * SROWW + kw + 4 + tig];
            }
            unsigned b[4][2];
#pragma unroll
            for (int nt = 0; nt < 4; nt++) {
                int n = wn * 32 + nt * 8;
                b[nt][0] = sB[(n + gid) * SROWW + kw + tig];
                b[nt][1] = sB[(n + gid) * SROWW + kw + 4 + tig];
            }
#pragma unroll
            for (int mt = 0; mt < 2; mt++)
#pragma unroll
                for (int nt = 0; nt < 4; nt++)
                    mma16816(acc[mt][nt][0], acc[mt][nt][1], acc[mt][nt][2], acc[mt][nt][3],
                             a[mt][0], a[mt][1], a[mt][2], a[mt][3],
                             b[nt][0], b[nt][1]);
        }
    }

    // ---- epilogue: direct float2 stores ----
#pragma unroll
    for (int mt = 0; mt < 2; mt++) {
        int r = row0 + wm * 32 + mt * 16 + gid;
#pragma unroll
        for (int nt = 0; nt < 4; nt++) {
            int cN = wn * 32 + nt * 8 + tig * 2;
            if (r < N_NODES)
                *(float2*)(OUT + (size_t)r * 128 + cN) = make_float2(acc[mt][nt][0], acc[mt][nt][1]);
            if (r + 8 < N_NODES)
                *(float2*)(OUT + (size_t)(r + 8) * 128 + cN) = make_float2(acc[mt][nt][2], acc[mt][nt][3]);
        }
    }
}

// ---------------- final GEMM: g_support2[N,40] = H[N,128] @ W10[128,40] ----------------
__global__ __launch_bounds__(256) void k_gemm40(const float* __restrict__ H,
                                                const float* __restrict__ W) {
    __shared__ float sW[128 * NCLASS];
    int tid = threadIdx.x;
    for (int i = tid; i < 128 * NCLASS; i += 256) sW[i] = W[i];
    __syncthreads();
    int row = blockIdx.x * 256 + tid;
    if (row >= N_NODES) return;
    float acc[NCLASS];
#pragma unroll
    for (int j = 0; j < NCLASS; j++) acc[j] = 0.f;
    for (int k = 0; k < 128; k += 4) {
        float4 h4 = __ldcs((const float4*)(H + (size_t)row * NF + k));
#pragma unroll
        for (int j4 = 0; j4 < 10; j4++) {
            float4 w0 = *(const float4*)&sW[(k + 0) * NCLASS + j4 * 4];
            float4 w1 = *(const float4*)&sW[(k + 1) * NCLASS + j4 * 4];
            float4 w2 = *(const float4*)&sW[(k + 2) * NCLASS + j4 * 4];
            float4 w3 = *(const float4*)&sW[(k + 3) * NCLASS + j4 * 4];
            acc[j4 * 4 + 0] += h4.x * w0.x + h4.y * w1.x + h4.z * w2.x + h4.w * w3.x;
            acc[j4 * 4 + 1] += h4.x * w0.y + h4.y * w1.y + h4.z * w2.y + h4.w * w3.y;
            acc[j4 * 4 + 2] += h4.x * w0.z + h4.y * w1.z + h4.z * w2.z + h4.w * w3.z;
            acc[j4 * 4 + 3] += h4.x * w0.w + h4.y * w1.w + h4.z * w2.w + h4.w * w3.w;
        }
    }
#pragma unroll
    for (int j = 0; j < NCLASS; j++) g_support2[(size_t)row * NCLASS + j] = acc[j];
}

// ---------------- SpMM + bias + relu (+residual), warp per node ----------------
// R12 version: predicated unroll-8 chunks.
__global__ __launch_bounds__(256) void k_spmm(const float* __restrict__ sup,
                                              const float* __restrict__ bias,
                                              int residual) {
    int gwarp = (blockIdx.x * blockDim.x + threadIdx.x) >> 5;
    int lane  = threadIdx.x & 31;
    if (gwarp >= N_NODES) return;
    int beg = g_rowptr[gwarp];
    int end = g_rowptr[gwarp + 1];
    float4 acc = make_float4(0.f, 0.f, 0.f, 0.f);
    int count = end - beg;
    for (int base = 0; base < count; base += 8) {
        int m = count - base;
        int s = 0; float w = 0.f;
        if (lane < 8 && lane < m) {
            int2 e = __ldcs(&g_edge[beg + base + lane]);
            s = e.x; w = __int_as_float(e.y);
        }
#pragma unroll
        for (int j = 0; j < 8; j++) {
            int   ss = __shfl_sync(0xffffffffu, s, j);
            float ww = __shfl_sync(0xffffffffu, w, j);
            if (j < m) {
                float4 v = *(const float4*)(sup + (size_t)ss * NF + lane * 4);
                acc.x += ww * v.x; acc.y += ww * v.y; acc.z += ww * v.z; acc.w += ww * v.w;
            }
        }
    }
    float4 b = *(const float4*)(bias + lane * 4);
    float4 r;
    r.x = fmaxf(acc.x + b.x, 0.f);
    r.y = fmaxf(acc.y + b.y, 0.f);
    r.z = fmaxf(acc.z + b.z, 0.f);
    r.w = fmaxf(acc.w + b.w, 0.f);
    float* hrow = g_h + (size_t)gwarp * NF + lane * 4;
    if (residual) {
        float4 hv = __ldcs((const float4*)hrow);
        r.x += hv.x; r.y += hv.y; r.z += hv.z; r.w += hv.w;
    }
    __stcs((float4*)hrow, r);
}

// ---------------- final SpMM(40) + bias + relu + log_softmax ----------------
__global__ __launch_bounds__(256) void k_spmm40_softmax(const float* __restrict__ b10,
                                                        float* __restrict__ out) {
    int gwarp = (blockIdx.x * blockDim.x + threadIdx.x) >> 5;
    int lane  = threadIdx.x & 31;
    if (gwarp >= N_NODES) return;
    int beg = g_rowptr[gwarp];
    int end = g_rowptr[gwarp + 1];
    float a0 = 0.f, a1 = 0.f;
    int count = end - beg;
    for (int base = 0; base < count; base += 8) {
        int m = count - base;
        int s = 0; float w = 0.f;
        if (lane < 8 && lane < m) {
            int2 e = __ldcs(&g_edge[beg + base + lane]);
            s = e.x; w = __int_as_float(e.y);
        }
#pragma unroll
        for (int j = 0; j < 8; j++) {
            int   ss = __shfl_sync(0xffffffffu, s, j);
            float ww = __shfl_sync(0xffffffffu, w, j);
            if (j < m) {
                a0 += ww * g_support2[(size_t)ss * NCLASS + lane];
                if (lane < 8) a1 += ww * g_support2[(size_t)ss * NCLASS + 32 + lane];
            }
        }
    }
    float v0 = fmaxf(a0 + b10[lane], 0.f);
    float v1 = (lane < 8) ? fmaxf(a1 + b10[32 + lane], 0.f) : -1e30f;
    float mx = fmaxf(v0, v1);
#pragma unroll
    for (int off = 16; off > 0; off >>= 1)
        mx = fmaxf(mx, __shfl_xor_sync(0xffffffffu, mx, off));
    float se = expf(v0 - mx) + ((lane < 8) ? expf(v1 - mx) : 0.f);
#pragma unroll
    for (int off = 16; off > 0; off >>= 1)
        se += __shfl_xor_sync(0xffffffffu, se, off);
    float ls = logf(se);
    out[(size_t)gwarp * NCLASS + lane] = v0 - mx - ls;
    if (lane < 8) out[(size_t)gwarp * NCLASS + 32 + lane] = v1 - mx - ls;
}

// ---------------- launcher ----------------
extern "C" void kernel_launch(void* const* d_in, const int* in_sizes, int n_in,
                              void* d_out, int out_size) {
    const float* x     = (const float*)d_in[0];
    const int*   src   = (const int*)d_in[1];
    const int*   dst   = (const int*)d_in[2];
    const float* ew    = (const float*)d_in[3];
    const float* W1    = (const float*)d_in[4];
    const float* W_hid = (const float*)d_in[5];
    const float* W10   = (const float*)d_in[6];
    const float* b1    = (const float*)d_in[7];
    const float* b_hid = (const float*)d_in[8];
    const float* b10   = (const float*)d_in[9];
    float* out = (float*)d_out;

    float *p_h, *p_sup;
    int* p_deg;
    __nv_bfloat16 *p_whi, *p_wlo;
    cudaGetSymbolAddress((void**)&p_h, g_h);
    cudaGetSymbolAddress((void**)&p_sup, g_support);
    cudaGetSymbolAddress((void**)&p_deg, g_deg);
    cudaGetSymbolAddress((void**)&p_whi, g_wt_hi);
    cudaGetSymbolAddress((void**)&p_wlo, g_wt_lo);

    cudaFuncSetAttribute(k_gemm_mma, cudaFuncAttributeMaxDynamicSharedMemorySize,
                         SMEM_GEMM_TOTAL);

    dim3 gs((N_NODES * 32 + 255) / 256);

    // Launch order keeps k_gemm_mma as the 4th kernel (ncu -s 5 -c 1 capture).
    cudaMemsetAsync(p_deg, 0, N_NODES * sizeof(int));
    k_count<<<(N_EDGES + 255) / 256, 256>>>(dst);      // 1
    k_scan<<<1, 1024>>>();                             // 2
    k_prep_w<<<(9 * 16384 + 255) / 256, 256>>>(W1, W_hid);  // 3
    k_gemm_mma<<<N_TILES, 512, SMEM_GEMM_TOTAL>>>(x, p_whi, p_wlo, p_sup);  // 4 <- profiled
    k_scatter<<<(N_EDGES + 255) / 256, 256>>>(src, dst, ew);                // 5
    k_spmm<<<gs, 256>>>(p_sup, b1, 0);                                      // 6

    // 8 hidden residual layers
    for (int i = 0; i < 8; i++) {
        k_gemm_mma<<<N_TILES, 512, SMEM_GEMM_TOTAL>>>(
            p_h, p_whi + (size_t)(i + 1) * 16384, p_wlo + (size_t)(i + 1) * 16384, p_sup);
        k_spmm<<<gs, 256>>>(p_sup, b_hid + (size_t)i * 128, 1);
    }

    // final layer + log_softmax
    k_gemm40<<<(N_NODES + 255) / 256, 256>>>(p_h, W10);
    k_spmm40_softmax<<<gs, 256>>>(b10, out);
}

// round 16
// speedup vs baseline: 1.1434x; 1.0508x over previous
#include <cuda_runtime.h>
#include <cuda_bf16.h>
#include <stdint.h>
#include <cstdint>
#include <math.h>

#define N_NODES 100000
#define N_EDGES 800000
#define NF 128
#define NCLASS 40
#define N_TILES ((N_NODES + 127) / 128)   // 782

// ---------------- persistent scratch (no allocation allowed) ----------------
__device__ float g_h[N_NODES * NF];
__device__ float g_support[N_NODES * NF];
__device__ float g_support2[N_NODES * NCLASS];
__device__ int   g_deg[N_NODES];
__device__ int   g_rowptr[N_NODES + 1];
__device__ int   g_cursor[N_NODES];
__device__ int2  g_edge[N_EDGES];           // CSR-by-dst: {src, weight-as-int}
__device__ __nv_bfloat16 g_wt_hi[9 * 128 * 128];
__device__ __nv_bfloat16 g_wt_lo[9 * 128 * 128];

// ---------------- mma.sync m16n8k16 bf16 ----------------
__device__ __forceinline__ void mma16816(float& d0, float& d1, float& d2, float& d3,
                                         unsigned a0, unsigned a1, unsigned a2, unsigned a3,
                                         unsigned b0, unsigned b1) {
    asm volatile(
        "mma.sync.aligned.m16n8k16.row.col.f32.bf16.bf16.f32 "
        "{%0,%1,%2,%3}, {%4,%5,%6,%7}, {%8,%9}, {%0,%1,%2,%3};"
        : "+f"(d0), "+f"(d1), "+f"(d2), "+f"(d3)
        : "r"(a0), "r"(a1), "r"(a2), "r"(a3), "r"(b0), "r"(b1));
}

// ---------------- CSR build ----------------
__global__ void k_count(const int* __restrict__ dst) {
    int e = blockIdx.x * blockDim.x + threadIdx.x;
    if (e < N_EDGES) atomicAdd(&g_deg[dst[e]], 1);
}

__global__ void k_scan() {
    __shared__ int sp[1024];
    const int CH = (N_NODES + 1023) / 1024;   // 98
    int t = threadIdx.x;
    int b = t * CH;
    int s = 0;
    for (int i = b; i < b + CH && i < N_NODES; i++) s += g_deg[i];
    sp[t] = s;
    __syncthreads();
    for (int off = 1; off < 1024; off <<= 1) {
        int v = 0;
        if (t >= off) v = sp[t - off];
        __syncthreads();
        sp[t] += v;
        __syncthreads();
    }
    int prefix = (t == 0) ? 0 : sp[t - 1];
    for (int i = b; i < b + CH && i < N_NODES; i++) {
        g_rowptr[i] = prefix;
        g_cursor[i] = prefix;
        prefix += g_deg[i];
    }
    if (t == 1023) g_rowptr[N_NODES] = sp[1023];
}

__global__ void k_scatter(const int* __restrict__ src, const int* __restrict__ dst,
                          const float* __restrict__ ew) {
    int e = blockIdx.x * blockDim.x + threadIdx.x;
    if (e < N_EDGES) {
        int d = dst[e];
        int pos = atomicAdd(&g_cursor[d], 1);
        g_edge[pos] = make_int2(src[e], __float_as_int(ew[e]));
    }
}

// ---------------- weight transpose + hi/lo split ----------------
__global__ void k_prep_w(const float* __restrict__ W1, const float* __restrict__ W_hid) {
    int idx = blockIdx.x * blockDim.x + threadIdx.x;
    if (idx >= 9 * 16384) return;
    int m = idx >> 14;
    int r = idx & 16383;
    int n = r >> 7;
    int k = r & 127;
    float w = (m == 0) ? W1[k * 128 + n] : W_hid[(size_t)(m - 1) * 16384 + k * 128 + n];
    __nv_bfloat16 hi = __float2bfloat16(w);
    __nv_bfloat16 lo = __float2bfloat16(w - __bfloat162float(hi));
    g_wt_hi[idx] = hi;
    g_wt_lo[idx] = lo;
}

// ---------------- split-bf16 tensor-core GEMM: 512 threads, merged 3-pass k-loop ----------------
#define SROW 136
#define SROWW 68
#define SM_BYTES (128 * SROW * 2)
#define SM_AHI 0
#define SM_ALO (SM_BYTES)
#define SM_BHI (2 * SM_BYTES)
#define SM_BLO (3 * SM_BYTES)
#define SMEM_GEMM_TOTAL (4 * SM_BYTES)   // 139264

__global__ void __launch_bounds__(512, 1)
k_gemm_mma(const float* __restrict__ H,
           const __nv_bfloat16* __restrict__ Bhi,
           const __nv_bfloat16* __restrict__ Blo,
           float* __restrict__ OUT) {
    extern __shared__ char smem[];
    int tid = threadIdx.x;
    int row0 = blockIdx.x * 128;

    // ---- fill: A fp32 -> hi/lo bf16, B bf16 copy; 2048 chunks over 512 threads ----
    for (int c = tid; c < 2048; c += 512) {
        int row = c >> 4;
        int k = (c & 15) << 3;
        unsigned boff = (unsigned)(row * (SROW * 2) + k * 2);

        int grow = row0 + row;
        float4 v0 = make_float4(0.f, 0.f, 0.f, 0.f), v1 = v0;
        if (grow < N_NODES) {
            v0 = __ldcs((const float4*)(H + (size_t)grow * NF + k));
            v1 = __ldcs((const float4*)(H + (size_t)grow * NF + k + 4));
        }
        float va[8] = {v0.x, v0.y, v0.z, v0.w, v1.x, v1.y, v1.z, v1.w};
        unsigned uh[4], ul[4];
#pragma unroll
        for (int i = 0; i < 4; i++) {
            __nv_bfloat16 h0 = __float2bfloat16(va[2 * i]);
            __nv_bfloat16 h1 = __float2bfloat16(va[2 * i + 1]);
            __nv_bfloat16 l0 = __float2bfloat16(va[2 * i] - __bfloat162float(h0));
            __nv_bfloat16 l1 = __float2bfloat16(va[2 * i + 1] - __bfloat162float(h1));
            uh[i] = (unsigned)__bfloat16_as_ushort(h0) | ((unsigned)__bfloat16_as_ushort(h1) << 16);
            ul[i] = (unsigned)__bfloat16_as_ushort(l0) | ((unsigned)__bfloat16_as_ushort(l1) << 16);
        }
        *(uint4*)(smem + SM_AHI + boff) = make_uint4(uh[0], uh[1], uh[2], uh[3]);
        *(uint4*)(smem + SM_ALO + boff) = make_uint4(ul[0], ul[1], ul[2], ul[3]);

        uint4 bh = *(const uint4*)(Bhi + (size_t)row * 128 + k);
        uint4 bl = *(const uint4*)(Blo + (size_t)row * 128 + k);
        *(uint4*)(smem + SM_BHI + boff) = bh;
        *(uint4*)(smem + SM_BLO + boff) = bl;
    }
    __syncthreads();

    // ---- warp tiling: 16 warps = 4 (m) x 4 (n); warp tile 32 x 32 ----
    int lane = tid & 31, w = tid >> 5;
    int wm = w & 3;          // rows wm*32
    int wn = w >> 2;         // cols wn*32
    int gid = lane >> 2;     // 0..7
    int tig = lane & 3;      // 0..3

    const unsigned* sAh = (const unsigned*)(smem + SM_AHI);
    const unsigned* sAl = (const unsigned*)(smem + SM_ALO);
    const unsigned* sBh = (const unsigned*)(smem + SM_BHI);
    const unsigned* sBl = (const unsigned*)(smem + SM_BLO);

    float acc[2][4][4];
#pragma unroll
    for (int mt = 0; mt < 2; mt++)
#pragma unroll
        for (int nt = 0; nt < 4; nt++)
#pragma unroll
            for (int i = 0; i < 4; i++) acc[mt][nt][i] = 0.f;

    // ---- merged k-loop: load hi+lo fragments once, 24 MMA per k-step ----
#pragma unroll
    for (int ks = 0; ks < 8; ks++) {
        int kw = ks * 8;
        unsigned ah[2][4], al[2][4];
#pragma unroll
        for (int mt = 0; mt < 2; mt++) {
            int r = wm * 32 + mt * 16;
            ah[mt][0] = sAh[(r + gid) * SROWW + kw + tig];
            ah[mt][1] = sAh[(r + gid + 8) * SROWW + kw + tig];
            ah[mt][2] = sAh[(r + gid) * SROWW + kw + 4 + tig];
            ah[mt][3] = sAh[(r + gid + 8) * SROWW + kw + 4 + tig];
            al[mt][0] = sAl[(r + gid) * SROWW + kw + tig];
            al[mt][1] = sAl[(r + gid + 8) * SROWW + kw + tig];
            al[mt][2] = sAl[(r + gid) * SROWW + kw + 4 + tig];
            al[mt][3] = sAl[(r + gid + 8) * SROWW + kw + 4 + tig];
        }
        unsigned bh[4][2], bl[4][2];
#pragma unroll
        for (int nt = 0; nt < 4; nt++) {
            int n = wn * 32 + nt * 8;
            bh[nt][0] = sBh[(n + gid) * SROWW + kw + tig];
            bh[nt][1] = sBh[(n + gid) * SROWW + kw + 4 + tig];
            bl[nt][0] = sBl[(n + gid) * SROWW + kw + tig];
            bl[nt][1] = sBl[(n + gid) * SROWW + kw + 4 + tig];
        }
#pragma unroll
        for (int mt = 0; mt < 2; mt++) {
#pragma unroll
            for (int nt = 0; nt < 4; nt++) {
                mma16816(acc[mt][nt][0], acc[mt][nt][1], acc[mt][nt][2], acc[mt][nt][3],
                         ah[mt][0], ah[mt][1], ah[mt][2], ah[mt][3],
                         bh[nt][0], bh[nt][1]);
                mma16816(acc[mt][nt][0], acc[mt][nt][1], acc[mt][nt][2], acc[mt][nt][3],
                         ah[mt][0], ah[mt][1], ah[mt][2], ah[mt][3],
                         bl[nt][0], bl[nt][1]);
                mma16816(acc[mt][nt][0], acc[mt][nt][1], acc[mt][nt][2], acc[mt][nt][3],
                         al[mt][0], al[mt][1], al[mt][2], al[mt][3],
                         bh[nt][0], bh[nt][1]);
            }
        }
    }

    // ---- epilogue: direct float2 stores ----
#pragma unroll
    for (int mt = 0; mt < 2; mt++) {
        int r = row0 + wm * 32 + mt * 16 + gid;
#pragma unroll
        for (int nt = 0; nt < 4; nt++) {
            int cN = wn * 32 + nt * 8 + tig * 2;
            if (r < N_NODES)
                *(float2*)(OUT + (size_t)r * 128 + cN) = make_float2(acc[mt][nt][0], acc[mt][nt][1]);
            if (r + 8 < N_NODES)
                *(float2*)(OUT + (size_t)(r + 8) * 128 + cN) = make_float2(acc[mt][nt][2], acc[mt][nt][3]);
        }
    }
}

// ---------------- final GEMM: g_support2[N,40] = H[N,128] @ W10[128,40] ----------------
__global__ __launch_bounds__(256) void k_gemm40(const float* __restrict__ H,
                                                const float* __restrict__ W) {
    __shared__ float sW[128 * NCLASS];
    int tid = threadIdx.x;
    for (int i = tid; i < 128 * NCLASS; i += 256) sW[i] = W[i];
    __syncthreads();
    int row = blockIdx.x * 256 + tid;
    if (row >= N_NODES) return;
    float acc[NCLASS];
#pragma unroll
    for (int j = 0; j < NCLASS; j++) acc[j] = 0.f;
    for (int k = 0; k < 128; k += 4) {
        float4 h4 = __ldcs((const float4*)(H + (size_t)row * NF + k));
#pragma unroll
        for (int j4 = 0; j4 < 10; j4++) {
            float4 w0 = *(const float4*)&sW[(k + 0) * NCLASS + j4 * 4];
            float4 w1 = *(const float4*)&sW[(k + 1) * NCLASS + j4 * 4];
            float4 w2 = *(const float4*)&sW[(k + 2) * NCLASS + j4 * 4];
            float4 w3 = *(const float4*)&sW[(k + 3) * NCLASS + j4 * 4];
            acc[j4 * 4 + 0] += h4.x * w0.x + h4.y * w1.x + h4.z * w2.x + h4.w * w3.x;
            acc[j4 * 4 + 1] += h4.x * w0.y + h4.y * w1.y + h4.z * w2.y + h4.w * w3.y;
            acc[j4 * 4 + 2] += h4.x * w0.z + h4.y * w1.z + h4.z * w2.z + h4.w * w3.z;
            acc[j4 * 4 + 3] += h4.x * w0.w + h4.y * w1.w + h4.z * w2.w + h4.w * w3.w;
        }
    }
#pragma unroll
    for (int j = 0; j < NCLASS; j++) g_support2[(size_t)row * NCLASS + j] = acc[j];
}

// ---------------- SpMM + bias + relu (+residual), warp per node ----------------
// R12 version: predicated unroll-8 chunks.
__global__ __launch_bounds__(256) void k_spmm(const float* __restrict__ sup,
                                              const float* __restrict__ bias,
                                              int residual) {
    int gwarp = (blockIdx.x * blockDim.x + threadIdx.x) >> 5;
    int lane  = threadIdx.x & 31;
    if (gwarp >= N_NODES) return;
    int beg = g_rowptr[gwarp];
    int end = g_rowptr[gwarp + 1];
    float4 acc = make_float4(0.f, 0.f, 0.f, 0.f);
    int count = end - beg;
    for (int base = 0; base < count; base += 8) {
        int m = count - base;
        int s = 0; float w = 0.f;
        if (lane < 8 && lane < m) {
            int2 e = __ldcs(&g_edge[beg + base + lane]);
            s = e.x; w = __int_as_float(e.y);
        }
#pragma unroll
        for (int j = 0; j < 8; j++) {
            int   ss = __shfl_sync(0xffffffffu, s, j);
            float ww = __shfl_sync(0xffffffffu, w, j);
            if (j < m) {
                float4 v = *(const float4*)(sup + (size_t)ss * NF + lane * 4);
                acc.x += ww * v.x; acc.y += ww * v.y; acc.z += ww * v.z; acc.w += ww * v.w;
            }
        }
    }
    float4 b = *(const float4*)(bias + lane * 4);
    float4 r;
    r.x = fmaxf(acc.x + b.x, 0.f);
    r.y = fmaxf(acc.y + b.y, 0.f);
    r.z = fmaxf(acc.z + b.z, 0.f);
    r.w = fmaxf(acc.w + b.w, 0.f);
    float* hrow = g_h + (size_t)gwarp * NF + lane * 4;
    if (residual) {
        float4 hv = __ldcs((const float4*)hrow);
        r.x += hv.x; r.y += hv.y; r.z += hv.z; r.w += hv.w;
    }
    __stcs((float4*)hrow, r);
}

// ---------------- final SpMM(40) + bias + relu + log_softmax ----------------
__global__ __launch_bounds__(256) void k_spmm40_softmax(const float* __restrict__ b10,
                                                        float* __restrict__ out) {
    int gwarp = (blockIdx.x * blockDim.x + threadIdx.x) >> 5;
    int lane  = threadIdx.x & 31;
    if (gwarp >= N_NODES) return;
    int beg = g_rowptr[gwarp];
    int end = g_rowptr[gwarp + 1];
    float a0 = 0.f, a1 = 0.f;
    int count = end - beg;
    for (int base = 0; base < count; base += 8) {
        int m = count - base;
        int s = 0; float w = 0.f;
        if (lane < 8 && lane < m) {
            int2 e = __ldcs(&g_edge[beg + base + lane]);
            s = e.x; w = __int_as_float(e.y);
        }
#pragma unroll
        for (int j = 0; j < 8; j++) {
            int   ss = __shfl_sync(0xffffffffu, s, j);
            float ww = __shfl_sync(0xffffffffu, w, j);
            if (j < m) {
                a0 += ww * g_support2[(size_t)ss * NCLASS + lane];
                if (lane < 8) a1 += ww * g_support2[(size_t)ss * NCLASS + 32 + lane];
            }
        }
    }
    float v0 = fmaxf(a0 + b10[lane], 0.f);
    float v1 = (lane < 8) ? fmaxf(a1 + b10[32 + lane], 0.f) : -1e30f;
    float mx = fmaxf(v0, v1);
#pragma unroll
    for (int off = 16; off > 0; off >>= 1)
        mx = fmaxf(mx, __shfl_xor_sync(0xffffffffu, mx, off));
    float se = expf(v0 - mx) + ((lane < 8) ? expf(v1 - mx) : 0.f);
#pragma unroll
    for (int off = 16; off > 0; off >>= 1)
        se += __shfl_xor_sync(0xffffffffu, se, off);
    float ls = logf(se);
    out[(size_t)gwarp * NCLASS + lane] = v0 - mx - ls;
    if (lane < 8) out[(size_t)gwarp * NCLASS + 32 + lane] = v1 - mx - ls;
}

// ---------------- launcher ----------------
extern "C" void kernel_launch(void* const* d_in, const int* in_sizes, int n_in,
                              void* d_out, int out_size) {
    const float* x     = (const float*)d_in[0];
    const int*   src   = (const int*)d_in[1];
    const int*   dst   = (const int*)d_in[2];
    const float* ew    = (const float*)d_in[3];
    const float* W1    = (const float*)d_in[4];
    const float* W_hid = (const float*)d_in[5];
    const float* W10   = (const float*)d_in[6];
    const float* b1    = (const float*)d_in[7];
    const float* b_hid = (const float*)d_in[8];
    const float* b10   = (const float*)d_in[9];
    float* out = (float*)d_out;

    float *p_h, *p_sup;
    int* p_deg;
    __nv_bfloat16 *p_whi, *p_wlo;
    cudaGetSymbolAddress((void**)&p_h, g_h);
    cudaGetSymbolAddress((void**)&p_sup, g_support);
    cudaGetSymbolAddress((void**)&p_deg, g_deg);
    cudaGetSymbolAddress((void**)&p_whi, g_wt_hi);
    cudaGetSymbolAddress((void**)&p_wlo, g_wt_lo);

    cudaFuncSetAttribute(k_gemm_mma, cudaFuncAttributeMaxDynamicSharedMemorySize,
                         SMEM_GEMM_TOTAL);

    dim3 gs((N_NODES * 32 + 255) / 256);

    // Launch order keeps k_gemm_mma as the 4th kernel (ncu -s 5 -c 1 capture).
    cudaMemsetAsync(p_deg, 0, N_NODES * sizeof(int));
    k_count<<<(N_EDGES + 255) / 256, 256>>>(dst);      // 1
    k_scan<<<1, 1024>>>();                             // 2
    k_prep_w<<<(9 * 16384 + 255) / 256, 256>>>(W1, W_hid);  // 3
    k_gemm_mma<<<N_TILES, 512, SMEM_GEMM_TOTAL>>>(x, p_whi, p_wlo, p_sup);  // 4 <- profiled
    k_scatter<<<(N_EDGES + 255) / 256, 256>>>(src, dst, ew);                // 5
    k_spmm<<<gs, 256>>>(p_sup, b1, 0);                                      // 6

    // 8 hidden residual layers
    for (int i = 0; i < 8; i++) {
        k_gemm_mma<<<N_TILES, 512, SMEM_GEMM_TOTAL>>>(
            p_h, p_whi + (size_t)(i + 1) * 16384, p_wlo + (size_t)(i + 1) * 16384, p_sup);
        k_spmm<<<gs, 256>>>(p_sup, b_hid + (size_t)i * 128, 1);
    }

    // final layer + log_softmax
    k_gemm40<<<(N_NODES + 255) / 256, 256>>>(p_h, W10);
    k_spmm40_softmax<<<gs, 256>>>(b10, out);
}

// round 17
// speedup vs baseline: 1.1550x; 1.0101x over previous
#include <cuda_runtime.h>
#include <cuda_bf16.h>
#include <stdint.h>
#include <cstdint>
#include <math.h>

#define N_NODES 100000
#define N_EDGES 800000
#define NF 128
#define NCLASS 40
#define N_TILES ((N_NODES + 127) / 128)   // 782

// ---------------- persistent scratch (no allocation allowed) ----------------
__device__ float g_h[N_NODES * NF];
__device__ float g_support[N_NODES * NF];
__device__ float g_support2[N_NODES * NCLASS];
__device__ int   g_deg[N_NODES];
__device__ int   g_rowptr[N_NODES + 1];
__device__ int   g_cursor[N_NODES];
__device__ int2  g_edge[N_EDGES];           // CSR-by-dst: {src, weight-as-int}
__device__ __nv_bfloat16 g_wt_hi[9 * 128 * 128];
__device__ __nv_bfloat16 g_wt_lo[9 * 128 * 128];

// ---------------- PTX helpers ----------------
__device__ __forceinline__ unsigned smem_u32(const void* p) {
    unsigned a;
    asm("{ .reg .u64 t; cvta.to.shared.u64 t, %1; cvt.u32.u64 %0, t; }" : "=r"(a) : "l"(p));
    return a;
}

__device__ __forceinline__ void mma16816(float& d0, float& d1, float& d2, float& d3,
                                         unsigned a0, unsigned a1, unsigned a2, unsigned a3,
                                         unsigned b0, unsigned b1) {
    asm volatile(
        "mma.sync.aligned.m16n8k16.row.col.f32.bf16.bf16.f32 "
        "{%0,%1,%2,%3}, {%4,%5,%6,%7}, {%8,%9}, {%0,%1,%2,%3};"
        : "+f"(d0), "+f"(d1), "+f"(d2), "+f"(d3)
        : "r"(a0), "r"(a1), "r"(a2), "r"(a3), "r"(b0), "r"(b1));
}

__device__ __forceinline__ void ldsm_x4(unsigned& r0, unsigned& r1, unsigned& r2, unsigned& r3,
                                        unsigned addr) {
    asm volatile("ldmatrix.sync.aligned.m8n8.x4.shared.b16 {%0,%1,%2,%3}, [%4];"
        : "=r"(r0), "=r"(r1), "=r"(r2), "=r"(r3) : "r"(addr));
}

// ---------------- CSR build ----------------
__global__ void k_count(const int* __restrict__ dst) {
    int e = blockIdx.x * blockDim.x + threadIdx.x;
    if (e < N_EDGES) atomicAdd(&g_deg[dst[e]], 1);
}

__global__ void k_scan() {
    __shared__ int sp[1024];
    const int CH = (N_NODES + 1023) / 1024;   // 98
    int t = threadIdx.x;
    int b = t * CH;
    int s = 0;
    for (int i = b; i < b + CH && i < N_NODES; i++) s += g_deg[i];
    sp[t] = s;
    __syncthreads();
    for (int off = 1; off < 1024; off <<= 1) {
        int v = 0;
        if (t >= off) v = sp[t - off];
        __syncthreads();
        sp[t] += v;
        __syncthreads();
    }
    int prefix = (t == 0) ? 0 : sp[t - 1];
    for (int i = b; i < b + CH && i < N_NODES; i++) {
        g_rowptr[i] = prefix;
        g_cursor[i] = prefix;
        prefix += g_deg[i];
    }
    if (t == 1023) g_rowptr[N_NODES] = sp[1023];
}

__global__ void k_scatter(const int* __restrict__ src, const int* __restrict__ dst,
                          const float* __restrict__ ew) {
    int e = blockIdx.x * blockDim.x + threadIdx.x;
    if (e < N_EDGES) {
        int d = dst[e];
        int pos = atomicAdd(&g_cursor[d], 1);
        g_edge[pos] = make_int2(src[e], __float_as_int(ew[e]));
    }
}

// ---------------- weight transpose + hi/lo split ----------------
__global__ void k_prep_w(const float* __restrict__ W1, const float* __restrict__ W_hid) {
    int idx = blockIdx.x * blockDim.x + threadIdx.x;
    if (idx >= 9 * 16384) return;
    int m = idx >> 14;
    int r = idx & 16383;
    int n = r >> 7;
    int k = r & 127;
    float w = (m == 0) ? W1[k * 128 + n] : W_hid[(size_t)(m - 1) * 16384 + k * 128 + n];
    __nv_bfloat16 hi = __float2bfloat16(w);
    __nv_bfloat16 lo = __float2bfloat16(w - __bfloat162float(hi));
    g_wt_hi[idx] = hi;
    g_wt_lo[idx] = lo;
}

// ---------------- split-bf16 tensor-core GEMM: 512 threads, ldmatrix fragments ----------------
#define SROW 136
#define SROWB (SROW * 2)               // 272 bytes per row
#define SM_BYTES (128 * SROWB)
#define SM_AHI 0
#define SM_ALO (SM_BYTES)
#define SM_BHI (2 * SM_BYTES)
#define SM_BLO (3 * SM_BYTES)
#define SMEM_GEMM_TOTAL (4 * SM_BYTES)   // 139264

__global__ void __launch_bounds__(512, 1)
k_gemm_mma(const float* __restrict__ H,
           const __nv_bfloat16* __restrict__ Bhi,
           const __nv_bfloat16* __restrict__ Blo,
           float* __restrict__ OUT) {
    extern __shared__ char smem[];
    int tid = threadIdx.x;
    int row0 = blockIdx.x * 128;

    // ---- fill: A fp32 -> hi/lo bf16, B bf16 copy; 2048 chunks over 512 threads ----
    for (int c = tid; c < 2048; c += 512) {
        int row = c >> 4;
        int k = (c & 15) << 3;
        unsigned boff = (unsigned)(row * SROWB + k * 2);

        int grow = row0 + row;
        float4 v0 = make_float4(0.f, 0.f, 0.f, 0.f), v1 = v0;
        if (grow < N_NODES) {
            v0 = __ldcs((const float4*)(H + (size_t)grow * NF + k));
            v1 = __ldcs((const float4*)(H + (size_t)grow * NF + k + 4));
        }
        float va[8] = {v0.x, v0.y, v0.z, v0.w, v1.x, v1.y, v1.z, v1.w};
        unsigned uh[4], ul[4];
#pragma unroll
        for (int i = 0; i < 4; i++) {
            __nv_bfloat16 h0 = __float2bfloat16(va[2 * i]);
            __nv_bfloat16 h1 = __float2bfloat16(va[2 * i + 1]);
            __nv_bfloat16 l0 = __float2bfloat16(va[2 * i] - __bfloat162float(h0));
            __nv_bfloat16 l1 = __float2bfloat16(va[2 * i + 1] - __bfloat162float(h1));
            uh[i] = (unsigned)__bfloat16_as_ushort(h0) | ((unsigned)__bfloat16_as_ushort(h1) << 16);
            ul[i] = (unsigned)__bfloat16_as_ushort(l0) | ((unsigned)__bfloat16_as_ushort(l1) << 16);
        }
        *(uint4*)(smem + SM_AHI + boff) = make_uint4(uh[0], uh[1], uh[2], uh[3]);
        *(uint4*)(smem + SM_ALO + boff) = make_uint4(ul[0], ul[1], ul[2], ul[3]);

        uint4 bh = *(const uint4*)(Bhi + (size_t)row * 128 + k);
        uint4 bl = *(const uint4*)(Blo + (size_t)row * 128 + k);
        *(uint4*)(smem + SM_BHI + boff) = bh;
        *(uint4*)(smem + SM_BLO + boff) = bl;
    }
    __syncthreads();

    // ---- warp tiling: 16 warps = 4 (m) x 4 (n); warp tile 32 x 32 ----
    int lane = tid & 31, w = tid >> 5;
    int wm = w & 3;          // rows wm*32
    int wn = w >> 2;         // cols wn*32
    unsigned sbase = smem_u32(smem);

    // ldmatrix per-lane base addresses
    // A tiles (per mt): t0=(r..r+7,k0) t1=(r+8..r+15,k0) t2=(r..r+7,k8) t3=(r+8..r+15,k8)
    int lA = lane & 15;
    int kA = (lane >= 16) ? 16 : 0;
    // B tiles (per nt-pair p): t0=(n..n+7,k0) t1=(n..n+7,k8) t2=(n+8..n+15,k0) t3=(n+8..n+15,k8)
    int lB = (lane & 7) + ((lane >= 16) ? 8 : 0);
    int kB = ((lane >> 3) & 1) * 16;

    unsigned aHi[2], aLo[2], bHi[2], bLo[2];
#pragma unroll
    for (int mt = 0; mt < 2; mt++) {
        int r = wm * 32 + mt * 16 + lA;
        aHi[mt] = sbase + SM_AHI + (unsigned)(r * SROWB + kA);
        aLo[mt] = sbase + SM_ALO + (unsigned)(r * SROWB + kA);
    }
#pragma unroll
    for (int p = 0; p < 2; p++) {
        int n = wn * 32 + p * 16 + lB;
        bHi[p] = sbase + SM_BHI + (unsigned)(n * SROWB + kB);
        bLo[p] = sbase + SM_BLO + (unsigned)(n * SROWB + kB);
    }

    float acc[2][4][4];
#pragma unroll
    for (int mt = 0; mt < 2; mt++)
#pragma unroll
        for (int nt = 0; nt < 4; nt++)
#pragma unroll
            for (int i = 0; i < 4; i++) acc[mt][nt][i] = 0.f;

    // ---- merged k-loop: 8 LDSM.x4 + 24 HMMA per k-step ----
#pragma unroll
    for (int ks = 0; ks < 8; ks++) {
        unsigned ko = (unsigned)(ks * 32);   // 16 bf16 = 32 bytes per k-step
        unsigned ah[2][4], al[2][4];
        unsigned bh[4][2], bl[4][2];
#pragma unroll
        for (int mt = 0; mt < 2; mt++) {
            ldsm_x4(ah[mt][0], ah[mt][1], ah[mt][2], ah[mt][3], aHi[mt] + ko);
            ldsm_x4(al[mt][0], al[mt][1], al[mt][2], al[mt][3], aLo[mt] + ko);
        }
#pragma unroll
        for (int p = 0; p < 2; p++) {
            ldsm_x4(bh[2 * p][0], bh[2 * p][1], bh[2 * p + 1][0], bh[2 * p + 1][1], bHi[p] + ko);
            ldsm_x4(bl[2 * p][0], bl[2 * p][1], bl[2 * p + 1][0], bl[2 * p + 1][1], bLo[p] + ko);
        }
#pragma unroll
        for (int mt = 0; mt < 2; mt++) {
#pragma unroll
            for (int nt = 0; nt < 4; nt++) {
                mma16816(acc[mt][nt][0], acc[mt][nt][1], acc[mt][nt][2], acc[mt][nt][3],
                         ah[mt][0], ah[mt][1], ah[mt][2], ah[mt][3],
                         bh[nt][0], bh[nt][1]);
                mma16816(acc[mt][nt][0], acc[mt][nt][1], acc[mt][nt][2], acc[mt][nt][3],
                         ah[mt][0], ah[mt][1], ah[mt][2], ah[mt][3],
                         bl[nt][0], bl[nt][1]);
                mma16816(acc[mt][nt][0], acc[mt][nt][1], acc[mt][nt][2], acc[mt][nt][3],
                         al[mt][0], al[mt][1], al[mt][2], al[mt][3],
                         bh[nt][0], bh[nt][1]);
            }
        }
    }

    // ---- epilogue: direct float2 stores ----
    int gid = lane >> 2;
    int tig = lane & 3;
#pragma unroll
    for (int mt = 0; mt < 2; mt++) {
        int r = row0 + wm * 32 + mt * 16 + gid;
#pragma unroll
        for (int nt = 0; nt < 4; nt++) {
            int cN = wn * 32 + nt * 8 + tig * 2;
            if (r < N_NODES)
                *(float2*)(OUT + (size_t)r * 128 + cN) = make_float2(acc[mt][nt][0], acc[mt][nt][1]);
            if (r + 8 < N_NODES)
                *(float2*)(OUT + (size_t)(r + 8) * 128 + cN) = make_float2(acc[mt][nt][2], acc[mt][nt][3]);
        }
    }
}

// ---------------- final GEMM: g_support2[N,40] = H[N,128] @ W10[128,40] ----------------
__global__ __launch_bounds__(256) void k_gemm40(const float* __restrict__ H,
                                                const float* __restrict__ W) {
    __shared__ float sW[128 * NCLASS];
    int tid = threadIdx.x;
    for (int i = tid; i < 128 * NCLASS; i += 256) sW[i] = W[i];
    __syncthreads();
    int row = blockIdx.x * 256 + tid;
    if (row >= N_NODES) return;
    float acc[NCLASS];
#pragma unroll
    for (int j = 0; j < NCLASS; j++) acc[j] = 0.f;
    for (int k = 0; k < 128; k += 4) {
        float4 h4 = __ldcs((const float4*)(H + (size_t)row * NF + k));
#pragma unroll
        for (int j4 = 0; j4 < 10; j4++) {
            float4 w0 = *(const float4*)&sW[(k + 0) * NCLASS + j4 * 4];
            float4 w1 = *(const float4*)&sW[(k + 1) * NCLASS + j4 * 4];
            float4 w2 = *(const float4*)&sW[(k + 2) * NCLASS + j4 * 4];
            float4 w3 = *(const float4*)&sW[(k + 3) * NCLASS + j4 * 4];
            acc[j4 * 4 + 0] += h4.x * w0.x + h4.y * w1.x + h4.z * w2.x + h4.w * w3.x;
            acc[j4 * 4 + 1] += h4.x * w0.y + h4.y * w1.y + h4.z * w2.y + h4.w * w3.y;
            acc[j4 * 4 + 2] += h4.x * w0.z + h4.y * w1.z + h4.z * w2.z + h4.w * w3.z;
            acc[j4 * 4 + 3] += h4.x * w0.w + h4.y * w1.w + h4.z * w2.w + h4.w * w3.w;
        }
    }
#pragma unroll
    for (int j = 0; j < NCLASS; j++) g_support2[(size_t)row * NCLASS + j] = acc[j];
}

// ---------------- SpMM + bias + relu (+residual), warp per node ----------------
__global__ __launch_bounds__(256) void k_spmm(const float* __restrict__ sup,
                                              const float* __restrict__ bias,
                                              int residual) {
    int gwarp = (blockIdx.x * blockDim.x + threadIdx.x) >> 5;
    int lane  = threadIdx.x & 31;
    if (gwarp >= N_NODES) return;
    int beg = g_rowptr[gwarp];
    int end = g_rowptr[gwarp + 1];
    float4 acc = make_float4(0.f, 0.f, 0.f, 0.f);
    int count = end - beg;
    for (int base = 0; base < count; base += 8) {
        int m = count - base;
        int s = 0; float w = 0.f;
        if (lane < 8 && lane < m) {
            int2 e = __ldcs(&g_edge[beg + base + lane]);
            s = e.x; w = __int_as_float(e.y);
        }
#pragma unroll
        for (int j = 0; j < 8; j++) {
            int   ss = __shfl_sync(0xffffffffu, s, j);
            float ww = __shfl_sync(0xffffffffu, w, j);
            if (j < m) {
                float4 v = *(const float4*)(sup + (size_t)ss * NF + lane * 4);
                acc.x += ww * v.x; acc.y += ww * v.y; acc.z += ww * v.z; acc.w += ww * v.w;
            }
        }
    }
    float4 b = *(const float4*)(bias + lane * 4);
    float4 r;
    r.x = fmaxf(acc.x + b.x, 0.f);
    r.y = fmaxf(acc.y + b.y, 0.f);
    r.z = fmaxf(acc.z + b.z, 0.f);
    r.w = fmaxf(acc.w + b.w, 0.f);
    float* hrow = g_h + (size_t)gwarp * NF + lane * 4;
    if (residual) {
        float4 hv = __ldcs((const float4*)hrow);
        r.x += hv.x; r.y += hv.y; r.z += hv.z; r.w += hv.w;
    }
    __stcs((float4*)hrow, r);
}

// ---------------- final SpMM(40) + bias + relu + log_softmax ----------------
__global__ __launch_bounds__(256) void k_spmm40_softmax(const float* __restrict__ b10,
                                                        float* __restrict__ out) {
    int gwarp = (blockIdx.x * blockDim.x + threadIdx.x) >> 5;
    int lane  = threadIdx.x & 31;
    if (gwarp >= N_NODES) return;
    int beg = g_rowptr[gwarp];
    int end = g_rowptr[gwarp + 1];
    float a0 = 0.f, a1 = 0.f;
    int count = end - beg;
    for (int base = 0; base < count; base += 8) {
        int m = count - base;
        int s = 0; float w = 0.f;
        if (lane < 8 && lane < m) {
            int2 e = __ldcs(&g_edge[beg + base + lane]);
            s = e.x; w = __int_as_float(e.y);
        }
#pragma unroll
        for (int j = 0; j < 8; j++) {
            int   ss = __shfl_sync(0xffffffffu, s, j);
            float ww = __shfl_sync(0xffffffffu, w, j);
            if (j < m) {
                a0 += ww * g_support2[(size_t)ss * NCLASS + lane];
                if (lane < 8) a1 += ww * g_support2[(size_t)ss * NCLASS + 32 + lane];
            }
        }
    }
    float v0 = fmaxf(a0 + b10[lane], 0.f);
    float v1 = (lane < 8) ? fmaxf(a1 + b10[32 + lane], 0.f) : -1e30f;
    float mx = fmaxf(v0, v1);
#pragma unroll
    for (int off = 16; off > 0; off >>= 1)
        mx = fmaxf(mx, __shfl_xor_sync(0xffffffffu, mx, off));
    float se = expf(v0 - mx) + ((lane < 8) ? expf(v1 - mx) : 0.f);
#pragma unroll
    for (int off = 16; off > 0; off >>= 1)
        se += __shfl_xor_sync(0xffffffffu, se, off);
    float ls = logf(se);
    out[(size_t)gwarp * NCLASS + lane] = v0 - mx - ls;
    if (lane < 8) out[(size_t)gwarp * NCLASS + 32 + lane] = v1 - mx - ls;
}

// ---------------- launcher ----------------
extern "C" void kernel_launch(void* const* d_in, const int* in_sizes, int n_in,
                              void* d_out, int out_size) {
    const float* x     = (const float*)d_in[0];
    const int*   src   = (const int*)d_in[1];
    const int*   dst   = (const int*)d_in[2];
    const float* ew    = (const float*)d_in[3];
    const float* W1    = (const float*)d_in[4];
    const float* W_hid = (const float*)d_in[5];
    const float* W10   = (const float*)d_in[6];
    const float* b1    = (const float*)d_in[7];
    const float* b_hid = (const float*)d_in[8];
    const float* b10   = (const float*)d_in[9];
    float* out = (float*)d_out;

    float *p_h, *p_sup;
    int* p_deg;
    __nv_bfloat16 *p_whi, *p_wlo;
    cudaGetSymbolAddress((void**)&p_h, g_h);
    cudaGetSymbolAddress((void**)&p_sup, g_support);
    cudaGetSymbolAddress((void**)&p_deg, g_deg);
    cudaGetSymbolAddress((void**)&p_whi, g_wt_hi);
    cudaGetSymbolAddress((void**)&p_wlo, g_wt_lo);

    cudaFuncSetAttribute(k_gemm_mma, cudaFuncAttributeMaxDynamicSharedMemorySize,
                         SMEM_GEMM_TOTAL);

    dim3 gs((N_NODES * 32 + 255) / 256);

    // Launch order keeps k_gemm_mma as the 4th kernel (ncu capture lands there).
    cudaMemsetAsync(p_deg, 0, N_NODES * sizeof(int));
    k_count<<<(N_EDGES + 255) / 256, 256>>>(dst);      // 1
    k_scan<<<1, 1024>>>();                             // 2
    k_prep_w<<<(9 * 16384 + 255) / 256, 256>>>(W1, W_hid);  // 3
    k_gemm_mma<<<N_TILES, 512, SMEM_GEMM_TOTAL>>>(x, p_whi, p_wlo, p_sup);  // 4 <- profiled
    k_scatter<<<(N_EDGES + 255) / 256, 256>>>(src, dst, ew);                // 5
    k_spmm<<<gs, 256>>>(p_sup, b1, 0);                                      // 6

    // 8 hidden residual layers
    for (int i = 0; i < 8; i++) {
        k_gemm_mma<<<N_TILES, 512, SMEM_GEMM_TOTAL>>>(
            p_h, p_whi + (size_t)(i + 1) * 16384, p_wlo + (size_t)(i + 1) * 16384, p_sup);
        k_spmm<<<gs, 256>>>(p_sup, b_hid + (size_t)i * 128, 1);
    }

    // final layer + log_softmax
    k_gemm40<<<(N_NODES + 255) / 256, 256>>>(p_h, W10);
    k_spmm40_softmax<<<gs, 256>>>(b10, out);
}